// round 2
// baseline (speedup 1.0000x reference)
#include <cuda_runtime.h>
#include <cstdint>
#include <cstddef>

#define B_   32
#define T_   4096
#define D_   512
#define G_   8
#define OUT_ 512
#define CHUNK 256

// Static device scratch (no allocations allowed).
__device__ float g_sums[B_ * G_ * D_];   // 512 KB
__device__ int   g_counts[B_ * G_];
__device__ int   g_mask_u8;              // 1 if key_padding_mask is byte-packed

// ---------------------------------------------------------------------------
// Kernel A: detect mask storage width. Byte-packed random bools make most
// 32-bit words > 1; int32 bools are always 0 or 1. Deterministic.
// ---------------------------------------------------------------------------
__global__ void detect_kernel(const unsigned int* __restrict__ mask_words) {
    int any = 0;
    for (int i = threadIdx.x; i < 2048; i += 256)
        if (mask_words[i] > 1u) any = 1;
    any = __syncthreads_or(any);
    if (threadIdx.x == 0) g_mask_u8 = any;
}

// ---------------------------------------------------------------------------
// Kernel 0: zero the scratch accumulators (graph replays require re-zeroing).
// ---------------------------------------------------------------------------
__global__ void zero_kernel() {
    int idx = blockIdx.x * blockDim.x + threadIdx.x;
    int stride = gridDim.x * blockDim.x;
    for (int i = idx; i < B_ * G_ * D_; i += stride) g_sums[i] = 0.0f;
    if (idx < B_ * G_) g_counts[idx] = 0;
}

// ---------------------------------------------------------------------------
// Kernel 1: segmented masked sum.
// grid = (T/CHUNK, B), block = 128. Each thread owns one float4 slice of D.
// Group code is UNIFORM across the block (depends only on t), so the switch
// over 8 register float4 accumulators is a uniform branch: per valid token
// the cost is one LDG.128 + 4 FADD. Padded tokens (~50%) are skipped
// entirely -> ~half the HBM traffic.
// ---------------------------------------------------------------------------
__global__ void __launch_bounds__(128)
reduce_kernel(const float* __restrict__ batch,
              const int* __restrict__ types,
              const void* __restrict__ pad_raw) {
    __shared__ int s_code[CHUNK];
    __shared__ int s_cnt[G_];

    const int tid = threadIdx.x;
    const int b   = blockIdx.y;
    const int t0  = blockIdx.x * CHUNK;
    const bool u8 = (g_mask_u8 != 0);
    const unsigned char* pad8 = (const unsigned char*)pad_raw;
    const int*           padi = (const int*)pad_raw;

    if (tid < G_) s_cnt[tid] = 0;
    __syncthreads();
    for (int i = tid; i < CHUNK; i += 128) {
        int t = t0 + i;
        int p = u8 ? (int)pad8[(size_t)b * T_ + t] : padi[(size_t)b * T_ + t];
        int c = p ? -1 : types[t];
        s_code[i] = c;
        if (c >= 0) atomicAdd(&s_cnt[c], 1);
    }
    __syncthreads();

    float4 a0 = {0,0,0,0}, a1 = {0,0,0,0}, a2 = {0,0,0,0}, a3 = {0,0,0,0};
    float4 a4 = {0,0,0,0}, a5 = {0,0,0,0}, a6 = {0,0,0,0}, a7 = {0,0,0,0};

    const float4* rows = reinterpret_cast<const float4*>(batch)
                       + ((size_t)b * T_ + t0) * (D_ / 4);

#define ACC(A, V) { A.x += V.x; A.y += V.y; A.z += V.z; A.w += V.w; }
#define STEP(ii) {                                                            \
        int c = s_code[ii];                                                   \
        if (c >= 0) {                                                         \
            float4 v = rows[(size_t)(ii) * (D_ / 4) + tid];                   \
            switch (c) {                                                      \
                case 0: ACC(a0, v); break;  case 1: ACC(a1, v); break;        \
                case 2: ACC(a2, v); break;  case 3: ACC(a3, v); break;        \
                case 4: ACC(a4, v); break;  case 5: ACC(a5, v); break;        \
                case 6: ACC(a6, v); break;  default: ACC(a7, v); break;       \
            }                                                                 \
        }                                                                     \
    }

    #pragma unroll 4
    for (int i = 0; i < CHUNK; ++i) STEP(i)
#undef STEP
#undef ACC

    // flush: spread-address scalar atomics, skipping empty groups
    float* base = g_sums + ((size_t)b * G_) * D_ + tid * 4;
#define FLUSH(gi, A)                                                          \
    if (s_cnt[gi] > 0) {                                                      \
        float* d = base + (gi) * D_;                                          \
        atomicAdd(d + 0, A.x); atomicAdd(d + 1, A.y);                         \
        atomicAdd(d + 2, A.z); atomicAdd(d + 3, A.w);                         \
    }
    FLUSH(0, a0) FLUSH(1, a1) FLUSH(2, a2) FLUSH(3, a3)
    FLUSH(4, a4) FLUSH(5, a5) FLUSH(6, a6) FLUSH(7, a7)
#undef FLUSH
    if (tid < G_ && s_cnt[tid] > 0) atomicAdd(&g_counts[b * G_ + tid], s_cnt[tid]);
}

// ---------------------------------------------------------------------------
// Kernel 2: means (on the fly) + per-group GEMM + bias.
// grid = (OUT/128, B/16, G) = 64 blocks, 256 threads.
// Block computes a 16(batch) x 128(out) tile for one group, smem-tiled over D.
// ---------------------------------------------------------------------------
__global__ void __launch_bounds__(256)
gemm_kernel(const float* __restrict__ W,
            const float* __restrict__ bias,
            float* __restrict__ out) {
    __shared__ __align__(16) float s_w[32 * 128];  // 16 KB
    __shared__ __align__(16) float s_m[16 * 32];
    __shared__ float s_inv[16];

    const int tid = threadIdx.x;
    const int g   = blockIdx.z;
    const int oc0 = blockIdx.x * 128;
    const int b0  = blockIdx.y * 16;

    if (tid < 16) {
        int cnt = g_counts[(b0 + tid) * G_ + g];
        s_inv[tid] = (cnt > 0) ? 1.0f / (float)cnt : 0.0f;   // empty group -> mean 0
    }

    const int r   = tid >> 4;          // batch row within tile
    const int cq4 = (tid & 15) * 2;    // float4 col base
    float acc[8] = {0.f, 0.f, 0.f, 0.f, 0.f, 0.f, 0.f, 0.f};

    for (int dc = 0; dc < D_; dc += 32) {
        __syncthreads();

        const float4* Wg4 = reinterpret_cast<const float4*>(
            W + (size_t)g * D_ * OUT_ + (size_t)dc * OUT_ + oc0);
        #pragma unroll
        for (int q = 0; q < 4; ++q) {
            int idx = tid + q * 256;
            int dr  = idx >> 5;
            int c4  = idx & 31;
            reinterpret_cast<float4*>(s_w)[dr * 32 + c4] = Wg4[(size_t)dr * 128 + c4];
        }
        #pragma unroll
        for (int q = 0; q < 2; ++q) {
            int idx = tid + q * 256;
            int mr  = idx >> 5;
            int md  = idx & 31;
            float s = g_sums[((size_t)(b0 + mr) * G_ + g) * D_ + dc + md];
            s_m[mr * 32 + md] = s * s_inv[mr];
        }
        __syncthreads();

        #pragma unroll
        for (int d = 0; d < 32; ++d) {
            float m = s_m[r * 32 + d];
            float4 w0 = reinterpret_cast<float4*>(s_w)[d * 32 + cq4];
            float4 w1 = reinterpret_cast<float4*>(s_w)[d * 32 + cq4 + 1];
            acc[0] += m * w0.x; acc[1] += m * w0.y; acc[2] += m * w0.z; acc[3] += m * w0.w;
            acc[4] += m * w1.x; acc[5] += m * w1.y; acc[6] += m * w1.z; acc[7] += m * w1.w;
        }
    }

    const int cb = (tid & 15) * 8;
    const float* bg = bias + (size_t)g * OUT_ + oc0 + cb;
    float* og = out + (((size_t)(b0 + r)) * G_ + g) * OUT_ + oc0 + cb;
    #pragma unroll
    for (int j = 0; j < 8; ++j) og[j] = acc[j] + bg[j];
}

// ---------------------------------------------------------------------------
extern "C" void kernel_launch(void* const* d_in, const int* in_sizes, int n_in,
                              void* d_out, int out_size) {
    const float* batch = (const float*)d_in[0];          // [B,T,D] f32
    const float* W     = (const float*)d_in[1];          // [G,D,OUT] f32
    const float* bias  = (const float*)d_in[2];          // [G,OUT] f32
    const int*   types = (const int*)d_in[3];            // [T] i32
    const void*  pad   = d_in[4];                        // [B,T] bool (width detected)
    float* out = (float*)d_out;                          // [B,G,OUT] f32

    detect_kernel<<<1, 256>>>((const unsigned int*)pad);
    zero_kernel<<<64, 256>>>();
    reduce_kernel<<<dim3(T_ / CHUNK, B_), 128>>>(batch, types, pad);
    gemm_kernel<<<dim3(OUT_ / 128, B_ / 16, G_), 256>>>(W, bias, out);
}

// round 7
// speedup vs baseline: 2.4873x; 2.4873x over previous
#include <cuda_runtime.h>
#include <cstdint>
#include <cstddef>

#define B_   32
#define T_   4096
#define D_   512
#define G_   8
#define OUT_ 512
#define CHUNK 256
#define DT_  128   // d-chunk per gemm block

// Static device scratch (no allocations allowed).
__device__ float g_sums[B_ * G_ * D_];   // 512 KB
__device__ int   g_counts[B_ * G_];
__device__ int   g_mask_u8;              // 1 if key_padding_mask is byte-packed

// ---------------------------------------------------------------------------
// Kernel A: detect mask storage width. Byte-packed random bools make most
// 32-bit words > 1; int32 bools are always 0 or 1. Deterministic.
// ---------------------------------------------------------------------------
__global__ void detect_kernel(const unsigned int* __restrict__ mask_words) {
    int any = 0;
    for (int i = threadIdx.x; i < 2048; i += 256)
        if (mask_words[i] > 1u) any = 1;
    any = __syncthreads_or(any);
    if (threadIdx.x == 0) g_mask_u8 = any;
}

// ---------------------------------------------------------------------------
// Kernel 0: zero scratch + initialize out with bias (gemm accumulates into it).
// ---------------------------------------------------------------------------
__global__ void zero_kernel(const float* __restrict__ bias, float* __restrict__ out) {
    int idx = blockIdx.x * blockDim.x + threadIdx.x;
    int stride = gridDim.x * blockDim.x;
    for (int i = idx; i < B_ * G_ * D_; i += stride) g_sums[i] = 0.0f;
    for (int i = idx; i < B_ * G_ * OUT_; i += stride)
        out[i] = bias[i & (G_ * OUT_ - 1)];              // i % (G*OUT), layout [b,g,o]
    if (idx < B_ * G_) g_counts[idx] = 0;
}

// ---------------------------------------------------------------------------
// Kernel 1: segmented masked sum, MLP-8.
// grid = (T/CHUNK, B), block = 128. Valid tokens are compacted into smem first
// (padded to a multiple of 8 with group=-1 sentinels), then the main loop
// issues 8 UNCONDITIONAL LDG.128s before any accumulation -> deep MLP.
// Padded tokens (~50%) are skipped entirely -> ~half the HBM traffic.
// ---------------------------------------------------------------------------
__global__ void __launch_bounds__(128)
reduce_kernel(const float* __restrict__ batch,
              const int* __restrict__ types,
              const void* __restrict__ pad_raw) {
    __shared__ int s_idx[CHUNK + 8];
    __shared__ int s_grp[CHUNK + 8];
    __shared__ int s_cnt[G_];
    __shared__ int s_nv;

    const int tid = threadIdx.x;
    const int b   = blockIdx.y;
    const int t0  = blockIdx.x * CHUNK;
    const bool u8 = (g_mask_u8 != 0);
    const unsigned char* pad8 = (const unsigned char*)pad_raw;
    const int*           padi = (const int*)pad_raw;

    if (tid < G_) s_cnt[tid] = 0;
    if (tid == 0) s_nv = 0;
    __syncthreads();
    for (int i = tid; i < CHUNK; i += 128) {
        int t = t0 + i;
        int p = u8 ? (int)pad8[(size_t)b * T_ + t] : padi[(size_t)b * T_ + t];
        if (!p) {
            int g = types[t];
            int slot = atomicAdd(&s_nv, 1);
            s_idx[slot] = i;
            s_grp[slot] = g;
            atomicAdd(&s_cnt[g], 1);
        }
    }
    __syncthreads();
    const int nv  = s_nv;
    const int nvp = (nv + 7) & ~7;
    if (tid == 0) {
        for (int j = nv; j < nvp; ++j) { s_idx[j] = 0; s_grp[j] = -1; }
    }
    __syncthreads();

    float4 a0 = {0,0,0,0}, a1 = {0,0,0,0}, a2 = {0,0,0,0}, a3 = {0,0,0,0};
    float4 a4 = {0,0,0,0}, a5 = {0,0,0,0}, a6 = {0,0,0,0}, a7 = {0,0,0,0};

    const float4* rows = reinterpret_cast<const float4*>(batch)
                       + ((size_t)b * T_ + t0) * (D_ / 4) + tid;

#define ACC(A, V) { A.x += V.x; A.y += V.y; A.z += V.z; A.w += V.w; }
#define SWACC(g, V)                                                            \
    switch (g) {                                                               \
        case 0: ACC(a0, V); break;  case 1: ACC(a1, V); break;                 \
        case 2: ACC(a2, V); break;  case 3: ACC(a3, V); break;                 \
        case 4: ACC(a4, V); break;  case 5: ACC(a5, V); break;                 \
        case 6: ACC(a6, V); break;  case 7: ACC(a7, V); break;                 \
        default: break;                                                        \
    }

    for (int i = 0; i < nvp; i += 8) {
        int j0 = s_idx[i+0], j1 = s_idx[i+1], j2 = s_idx[i+2], j3 = s_idx[i+3];
        int j4 = s_idx[i+4], j5 = s_idx[i+5], j6 = s_idx[i+6], j7 = s_idx[i+7];
        int c0 = s_grp[i+0], c1 = s_grp[i+1], c2 = s_grp[i+2], c3 = s_grp[i+3];
        int c4 = s_grp[i+4], c5 = s_grp[i+5], c6 = s_grp[i+6], c7 = s_grp[i+7];
        // 8 unconditional loads, issued before any consumer -> MLP 8
        float4 v0 = rows[(size_t)j0 * (D_/4)];
        float4 v1 = rows[(size_t)j1 * (D_/4)];
        float4 v2 = rows[(size_t)j2 * (D_/4)];
        float4 v3 = rows[(size_t)j3 * (D_/4)];
        float4 v4 = rows[(size_t)j4 * (D_/4)];
        float4 v5 = rows[(size_t)j5 * (D_/4)];
        float4 v6 = rows[(size_t)j6 * (D_/4)];
        float4 v7 = rows[(size_t)j7 * (D_/4)];
        SWACC(c0, v0) SWACC(c1, v1) SWACC(c2, v2) SWACC(c3, v3)
        SWACC(c4, v4) SWACC(c5, v5) SWACC(c6, v6) SWACC(c7, v7)
    }
#undef SWACC
#undef ACC

    // flush: spread-address scalar atomics, skipping empty groups
    float* base = g_sums + ((size_t)b * G_) * D_ + tid * 4;
#define FLUSH(gi, A)                                                           \
    if (s_cnt[gi] > 0) {                                                       \
        float* d = base + (gi) * D_;                                           \
        atomicAdd(d + 0, A.x); atomicAdd(d + 1, A.y);                          \
        atomicAdd(d + 2, A.z); atomicAdd(d + 3, A.w);                          \
    }
    FLUSH(0, a0) FLUSH(1, a1) FLUSH(2, a2) FLUSH(3, a3)
    FLUSH(4, a4) FLUSH(5, a5) FLUSH(6, a6) FLUSH(7, a7)
#undef FLUSH
    if (tid < G_ && s_cnt[tid] > 0) atomicAdd(&g_counts[b * G_ + tid], s_cnt[tid]);
}

// ---------------------------------------------------------------------------
// Kernel 2: means + per-group GEMM (split-D, accumulate into bias-initialized
// out via atomics).
// grid = (OUT/64, G, D/128) = (8, 8, 4) = 256 blocks, 256 threads.
// Thread = 1 output column x 32 batches (32 reg accumulators). Means staged
// transposed in smem (d-major, pad 36), W read coalesced straight from DRAM.
// ---------------------------------------------------------------------------
__global__ void __launch_bounds__(256)
gemm_kernel(const float* __restrict__ W, float* __restrict__ out) {
    __shared__ __align__(16) float s_m[DT_ * 36];   // 18 KB, pad 36 (16B aligned rows)
    __shared__ float s_inv[B_];

    const int tid = threadIdx.x;
    const int oc0 = blockIdx.x * 64;
    const int g   = blockIdx.y;
    const int d0  = blockIdx.z * DT_;

    if (tid < B_) {
        int cnt = g_counts[tid * G_ + g];
        s_inv[tid] = (cnt > 0) ? 1.0f / (float)cnt : 0.0f;   // empty group -> mean 0
    }
    __syncthreads();

    // stage means transposed: s_m[d*36 + b]  (coalesced g_sums reads)
    for (int idx = tid; idx < B_ * DT_; idx += 256) {
        int bb = idx >> 7;          // 0..31
        int d  = idx & (DT_ - 1);   // 0..127
        s_m[d * 36 + bb] = g_sums[((size_t)bb * G_ + g) * D_ + d0 + d] * s_inv[bb];
    }
    __syncthreads();

    const int o     = oc0 + (tid & 63);
    const int dbase = tid >> 6;     // 0..3

    float acc[32];
    #pragma unroll
    for (int i = 0; i < 32; ++i) acc[i] = 0.0f;

    const float* Wp = W + ((size_t)g * D_ + d0 + dbase) * OUT_ + o;
    #pragma unroll 8
    for (int k = 0; k < 32; ++k) {
        float w = Wp[(size_t)k * 4 * OUT_];
        const float* mrow = &s_m[(dbase + 4 * k) * 36];
        #pragma unroll
        for (int q = 0; q < 8; ++q) {
            float4 m = *(const float4*)(mrow + q * 4);   // broadcast across warp
            acc[q * 4 + 0] += w * m.x;
            acc[q * 4 + 1] += w * m.y;
            acc[q * 4 + 2] += w * m.z;
            acc[q * 4 + 3] += w * m.w;
        }
    }

    #pragma unroll
    for (int bb = 0; bb < 32; ++bb)
        atomicAdd(&out[((size_t)bb * G_ + g) * OUT_ + o], acc[bb]);
}

// ---------------------------------------------------------------------------
extern "C" void kernel_launch(void* const* d_in, const int* in_sizes, int n_in,
                              void* d_out, int out_size) {
    const float* batch = (const float*)d_in[0];          // [B,T,D] f32
    const float* W     = (const float*)d_in[1];          // [G,D,OUT] f32
    const float* bias  = (const float*)d_in[2];          // [G,OUT] f32
    const int*   types = (const int*)d_in[3];            // [T] i32
    const void*  pad   = d_in[4];                        // [B,T] bool (width detected)
    float* out = (float*)d_out;                          // [B,G,OUT] f32

    detect_kernel<<<1, 256>>>((const unsigned int*)pad);
    zero_kernel<<<256, 256>>>(bias, out);
    reduce_kernel<<<dim3(T_ / CHUNK, B_), 128>>>(batch, types, pad);
    gemm_kernel<<<dim3(OUT_ / 64, G_, D_ / DT_), 256>>>(W, out);
}